// round 5
// baseline (speedup 1.0000x reference)
#include <cuda_runtime.h>

#define VOCAB   16384
#define WIDTH   256
#define NTOK    8224      // 32 * (1 + 256)
#define MPAD    8320      // 65 * 128 (GEMM M padding)
#define NBATCH  32

// ---------------- scratch (device globals; no runtime alloc) ----------------
__device__ float               g_xn[MPAD * WIDTH];     // normalized tokens (rows >= NTOK zeroed)
__device__ float               g_wn[VOCAB * WIDTH];    // normalized codebook
__device__ unsigned long long  g_best[NTOK];           // packed (key32 << 32) | (~col)
__device__ int                 g_used[VOCAB];
__device__ double              g_loss;

// ---------------- helpers ----------------
__device__ __forceinline__ float block_reduce_sum_256(float v) {
    __shared__ float red[8];
    const int lane = threadIdx.x & 31;
    const int w    = threadIdx.x >> 5;
    #pragma unroll
    for (int o = 16; o > 0; o >>= 1) v += __shfl_xor_sync(0xffffffffu, v, o);
    if (lane == 0) red[w] = v;
    __syncthreads();
    float s = 0.f;
    #pragma unroll
    for (int i = 0; i < 8; i++) s += red[i];
    return s;   // all threads get the same deterministic value
}

// monotonic float -> uint key (order-preserving for all finite floats)
__device__ __forceinline__ unsigned int f2key(float v) {
    unsigned int u = __float_as_uint(v);
    return (u & 0x80000000u) ? ~u : (u | 0x80000000u);
}

// ---------------- K0: reset per-call state ----------------
__global__ void k_init() {
    const int i = blockIdx.x * blockDim.x + threadIdx.x;
    if (i < NTOK)  g_best[i] = 0ull;
    if (i < VOCAB) g_used[i] = 0;
    if (i == 0)    g_loss    = 0.0;
}

// ---------------- K1: gather + L2-normalize tokens and codebook ----------------
// grid.x = MPAD + VOCAB blocks, 256 threads (thread = channel c)
__global__ void k_normalize(const float* __restrict__ cls,
                            const float* __restrict__ patch,
                            const float* __restrict__ W) {
    const int r = blockIdx.x;
    const int c = threadIdx.x;
    if (r < MPAD) {
        float v = 0.f;
        if (r < NTOK) {
            const int b = r / 257, j = r % 257;
            v = (j == 0) ? cls[b * WIDTH + c]
                         : patch[b * 65536 + c * 256 + (j - 1)];
        }
        const float s   = block_reduce_sum_256(v * v);
        const float inv = 1.f / fmaxf(sqrtf(s), 1e-12f);
        g_xn[r * WIDTH + c] = v * inv;
    } else {
        const int wr = r - MPAD;
        const float v   = W[wr * WIDTH + c];
        const float s   = block_reduce_sum_256(v * v);
        const float inv = 1.f / fmaxf(sqrtf(s), 1e-12f);
        g_wn[wr * WIDTH + c] = v * inv;
    }
}

// ---------------- K2: fp32 SGEMM (xn @ wn^T) with fused per-row argmax ----------------
// CTA tile 128x128, BK=8 double-buffered, 256 threads, 8x8 per thread.
// warps 2(m) x 4(n); lanes 8(m) x 4(n); fragments split 4+4 (m: +0/+32, n: +0/+16)
// for conflict-free LDS.128.
__global__ __launch_bounds__(256, 2)
void k_gemm_argmax() {
    __shared__ float As[2][8][128];
    __shared__ float Bs[2][8][128];
    __shared__ unsigned long long sbest[128];

    const int tid = threadIdx.x;
    const int bn  = blockIdx.x * 128;   // vocab tile (128 tiles)
    const int bm  = blockIdx.y * 128;   // token tile (65 tiles, M padded)

    // global->smem loader mapping: one float4 of A and one of B per thread
    const int ldrow = tid >> 1;           // 0..127
    const int ldk   = (tid & 1) * 4;      // 0 or 4

    // compute mapping
    const int warp = tid >> 5;
    const int lane = tid & 31;
    const int m0   = (warp >> 2) * 64 + (lane >> 2) * 4;  // row frag base
    const int n0   = (warp & 3)  * 32 + (lane & 3)  * 4;  // col frag base

    const float* Ap = g_xn + (bm + ldrow) * WIDTH + ldk;
    const float* Bp = g_wn + (bn + ldrow) * WIDTH + ldk;

    float acc[8][8];
    #pragma unroll
    for (int i = 0; i < 8; i++)
        #pragma unroll
        for (int j = 0; j < 8; j++) acc[i][j] = 0.f;

    // prologue: stage k-tile 0
    float4 av = *(const float4*)Ap;
    float4 bv = *(const float4*)Bp;
    As[0][ldk + 0][ldrow] = av.x; As[0][ldk + 1][ldrow] = av.y;
    As[0][ldk + 2][ldrow] = av.z; As[0][ldk + 3][ldrow] = av.w;
    Bs[0][ldk + 0][ldrow] = bv.x; Bs[0][ldk + 1][ldrow] = bv.y;
    Bs[0][ldk + 2][ldrow] = bv.z; Bs[0][ldk + 3][ldrow] = bv.w;
    __syncthreads();

    #pragma unroll 1
    for (int kt = 0; kt < 32; kt++) {          // 32 k-tiles of 8 => K=256
        const int buf = kt & 1;
        if (kt < 31) {                          // prefetch next tile to regs
            av = *(const float4*)(Ap + (kt + 1) * 8);
            bv = *(const float4*)(Bp + (kt + 1) * 8);
        }
        #pragma unroll
        for (int k = 0; k < 8; k++) {
            float a[8], b[8];
            *(float4*)&a[0] = *(const float4*)&As[buf][k][m0];
            *(float4*)&a[4] = *(const float4*)&As[buf][k][m0 + 32];
            *(float4*)&b[0] = *(const float4*)&Bs[buf][k][n0];
            *(float4*)&b[4] = *(const float4*)&Bs[buf][k][n0 + 16];
            #pragma unroll
            for (int i = 0; i < 8; i++)
                #pragma unroll
                for (int j = 0; j < 8; j++)
                    acc[i][j] = fmaf(a[i], b[j], acc[i][j]);
        }
        if (kt < 31) {
            const int nb = buf ^ 1;
            As[nb][ldk + 0][ldrow] = av.x; As[nb][ldk + 1][ldrow] = av.y;
            As[nb][ldk + 2][ldrow] = av.z; As[nb][ldk + 3][ldrow] = av.w;
            Bs[nb][ldk + 0][ldrow] = bv.x; Bs[nb][ldk + 1][ldrow] = bv.y;
            Bs[nb][ldk + 2][ldrow] = bv.z; Bs[nb][ldk + 3][ldrow] = bv.w;
            __syncthreads();
        }
    }

    // ---- fused argmax epilogue ----
    if (tid < 128) sbest[tid] = 0ull;
    __syncthreads();

    #pragma unroll
    for (int i = 0; i < 8; i++) {
        float bestv = acc[i][0];
        int   bj    = 0;
        #pragma unroll
        for (int j = 1; j < 8; j++)             // cols ascend in j -> '>' keeps lowest idx on tie
            if (acc[i][j] > bestv) { bestv = acc[i][j]; bj = j; }
        const int gcol = bn + n0 + ((bj < 4) ? bj : 12 + bj);
        const unsigned long long pk =
            ((unsigned long long)f2key(bestv) << 32) |
            (unsigned long long)(0xFFFFFFFFu - (unsigned int)gcol);  // smaller idx wins ties
        const int lrow = m0 + ((i < 4) ? i : 28 + i);
        atomicMax(&sbest[lrow], pk);
    }
    __syncthreads();

    if (tid < 128) {
        const int grow = bm + tid;
        if (grow < NTOK) atomicMax(&g_best[grow], sbest[tid]);
    }
}

// ---------------- K3: gather W[idx], write outputs, loss + usage marking ----------------
// block = token, thread = channel
__global__ void k_output(const float* __restrict__ cls,
                         const float* __restrict__ patch,
                         const float* __restrict__ W,
                         float* __restrict__ out) {
    const int t = blockIdx.x;
    const int c = threadIdx.x;
    const int b = t / 257, j = t % 257;

    const int code = (int)(0xFFFFFFFFu - (unsigned int)(g_best[t] & 0xFFFFFFFFull));
    const float w = W[code * WIDTH + c];                   // coalesced row read
    const float x = (j == 0) ? cls[b * WIDTH + c]
                             : patch[b * 65536 + c * 256 + (j - 1)];
    const float d = w - x;
    const float s = block_reduce_sum_256(d * d);
    if (c == 0) {
        atomicAdd(&g_loss, (double)s);
        g_used[code] = 1;
    }
    if (j == 0) out[b * WIDTH + c] = w;                         // fhat_class [B,1,C]
    else        out[8192 + b * 65536 + c * 256 + (j - 1)] = w;  // fhat_patch [B,C,H,W]
}

// ---------------- K4: scalars ----------------
__global__ void k_finalize(float* __restrict__ out) {
    int cnt = 0;
    for (int i = threadIdx.x; i < VOCAB; i += 256) cnt += g_used[i];
    const float s = block_reduce_sum_256((float)cnt);   // exact for <= 16384
    if (threadIdx.x == 0) {
        // vq_loss = (1 + BETA) * mean((W[idx]-x)^2), BETA = 0.25
        out[2105344] = (float)(1.25 * g_loss / (double)(NTOK * WIDTH));
        out[2105345] = 100.0f * s / (float)VOCAB;       // vocab usage %
    }
}

// ---------------- launch ----------------
extern "C" void kernel_launch(void* const* d_in, const int* in_sizes, int n_in,
                              void* d_out, int out_size) {
    // identify inputs by element count (sizes are pairwise distinct)
    const float* cls   = nullptr;   // 32*1*256      = 8192
    const float* patch = nullptr;   // 32*256*16*16  = 2097152
    const float* W     = nullptr;   // 16384*256     = 4194304
    for (int i = 0; i < n_in; i++) {
        if      (in_sizes[i] == NBATCH * WIDTH)          cls   = (const float*)d_in[i];
        else if (in_sizes[i] == NBATCH * WIDTH * 256)    patch = (const float*)d_in[i];
        else if (in_sizes[i] == VOCAB * WIDTH)           W     = (const float*)d_in[i];
    }
    float* out = (float*)d_out;

    k_init<<<VOCAB / 256, 256>>>();
    k_normalize<<<MPAD + VOCAB, 256>>>(cls, patch, W);
    dim3 grid(VOCAB / 128, MPAD / 128);   // (128, 65)
    k_gemm_argmax<<<grid, 256>>>();
    k_output<<<NTOK, 256>>>(cls, patch, W, out);
    k_finalize<<<1, 256>>>(out);
}

// round 6
// speedup vs baseline: 1.0015x; 1.0015x over previous
#include <cuda_runtime.h>

#define VOCAB   16384
#define WIDTH   256
#define NTOK    8224      // 32 * (1 + 256)
#define MPAD    8320      // 65 * 128 (GEMM M padding)
#define NBATCH  32

// ---------------- scratch (device globals; no runtime alloc) ----------------
__device__ float               g_xn[MPAD * WIDTH];     // normalized tokens (rows >= NTOK zeroed)
__device__ float               g_wn[VOCAB * WIDTH];    // normalized codebook
__device__ unsigned long long  g_best[NTOK];           // packed (key32 << 32) | (~col)
__device__ int                 g_used[VOCAB];
__device__ double              g_loss;

// ---------------- helpers ----------------
__device__ __forceinline__ float block_reduce_sum_256(float v) {
    __shared__ float red[8];
    const int lane = threadIdx.x & 31;
    const int w    = threadIdx.x >> 5;
    #pragma unroll
    for (int o = 16; o > 0; o >>= 1) v += __shfl_xor_sync(0xffffffffu, v, o);
    if (lane == 0) red[w] = v;
    __syncthreads();
    float s = 0.f;
    #pragma unroll
    for (int i = 0; i < 8; i++) s += red[i];
    return s;   // all threads get the same deterministic value
}

// monotonic float -> uint key (order-preserving for all finite floats)
__device__ __forceinline__ unsigned int f2key(float v) {
    unsigned int u = __float_as_uint(v);
    return (u & 0x80000000u) ? ~u : (u | 0x80000000u);
}

// ---------------- K0: reset per-call state ----------------
__global__ void k_init() {
    const int i = blockIdx.x * blockDim.x + threadIdx.x;
    if (i < NTOK)  g_best[i] = 0ull;
    if (i < VOCAB) g_used[i] = 0;
    if (i == 0)    g_loss    = 0.0;
}

// ---------------- K1: gather + L2-normalize tokens and codebook ----------------
// grid.x = MPAD + VOCAB blocks, 256 threads (thread = channel c)
__global__ void k_normalize(const float* __restrict__ cls,
                            const float* __restrict__ patch,
                            const float* __restrict__ W) {
    const int r = blockIdx.x;
    const int c = threadIdx.x;
    if (r < MPAD) {
        float v = 0.f;
        if (r < NTOK) {
            const int b = r / 257, j = r % 257;
            v = (j == 0) ? cls[b * WIDTH + c]
                         : patch[b * 65536 + c * 256 + (j - 1)];
        }
        const float s   = block_reduce_sum_256(v * v);
        const float inv = 1.f / fmaxf(sqrtf(s), 1e-12f);
        g_xn[r * WIDTH + c] = v * inv;
    } else {
        const int wr = r - MPAD;
        const float v   = W[wr * WIDTH + c];
        const float s   = block_reduce_sum_256(v * v);
        const float inv = 1.f / fmaxf(sqrtf(s), 1e-12f);
        g_wn[wr * WIDTH + c] = v * inv;
    }
}

// ---------------- K2: fp32 SGEMM (xn @ wn^T) with fused per-row argmax ----------------
// CTA tile 128x128, BK=8 double-buffered, 256 threads, 8x8 per thread.
// warps 2(m) x 4(n); lanes 8(m) x 4(n); fragments split 4+4 (m: +0/+32, n: +0/+16)
// for conflict-free LDS.128.
__global__ __launch_bounds__(256, 2)
void k_gemm_argmax() {
    __shared__ float As[2][8][128];
    __shared__ float Bs[2][8][128];
    __shared__ unsigned long long sbest[128];

    const int tid = threadIdx.x;
    const int bn  = blockIdx.x * 128;   // vocab tile (128 tiles)
    const int bm  = blockIdx.y * 128;   // token tile (65 tiles, M padded)

    // global->smem loader mapping: one float4 of A and one of B per thread
    const int ldrow = tid >> 1;           // 0..127
    const int ldk   = (tid & 1) * 4;      // 0 or 4

    // compute mapping
    const int warp = tid >> 5;
    const int lane = tid & 31;
    const int m0   = (warp >> 2) * 64 + (lane >> 2) * 4;  // row frag base
    const int n0   = (warp & 3)  * 32 + (lane & 3)  * 4;  // col frag base

    const float* Ap = g_xn + (bm + ldrow) * WIDTH + ldk;
    const float* Bp = g_wn + (bn + ldrow) * WIDTH + ldk;

    float acc[8][8];
    #pragma unroll
    for (int i = 0; i < 8; i++)
        #pragma unroll
        for (int j = 0; j < 8; j++) acc[i][j] = 0.f;

    // prologue: stage k-tile 0
    float4 av = *(const float4*)Ap;
    float4 bv = *(const float4*)Bp;
    As[0][ldk + 0][ldrow] = av.x; As[0][ldk + 1][ldrow] = av.y;
    As[0][ldk + 2][ldrow] = av.z; As[0][ldk + 3][ldrow] = av.w;
    Bs[0][ldk + 0][ldrow] = bv.x; Bs[0][ldk + 1][ldrow] = bv.y;
    Bs[0][ldk + 2][ldrow] = bv.z; Bs[0][ldk + 3][ldrow] = bv.w;
    __syncthreads();

    #pragma unroll 1
    for (int kt = 0; kt < 32; kt++) {          // 32 k-tiles of 8 => K=256
        const int buf = kt & 1;
        if (kt < 31) {                          // prefetch next tile to regs
            av = *(const float4*)(Ap + (kt + 1) * 8);
            bv = *(const float4*)(Bp + (kt + 1) * 8);
        }
        #pragma unroll
        for (int k = 0; k < 8; k++) {
            float a[8], b[8];
            *(float4*)&a[0] = *(const float4*)&As[buf][k][m0];
            *(float4*)&a[4] = *(const float4*)&As[buf][k][m0 + 32];
            *(float4*)&b[0] = *(const float4*)&Bs[buf][k][n0];
            *(float4*)&b[4] = *(const float4*)&Bs[buf][k][n0 + 16];
            #pragma unroll
            for (int i = 0; i < 8; i++)
                #pragma unroll
                for (int j = 0; j < 8; j++)
                    acc[i][j] = fmaf(a[i], b[j], acc[i][j]);
        }
        if (kt < 31) {
            const int nb = buf ^ 1;
            As[nb][ldk + 0][ldrow] = av.x; As[nb][ldk + 1][ldrow] = av.y;
            As[nb][ldk + 2][ldrow] = av.z; As[nb][ldk + 3][ldrow] = av.w;
            Bs[nb][ldk + 0][ldrow] = bv.x; Bs[nb][ldk + 1][ldrow] = bv.y;
            Bs[nb][ldk + 2][ldrow] = bv.z; Bs[nb][ldk + 3][ldrow] = bv.w;
            __syncthreads();
        }
    }

    // ---- fused argmax epilogue ----
    if (tid < 128) sbest[tid] = 0ull;
    __syncthreads();

    #pragma unroll
    for (int i = 0; i < 8; i++) {
        float bestv = acc[i][0];
        int   bj    = 0;
        #pragma unroll
        for (int j = 1; j < 8; j++)             // cols ascend in j -> '>' keeps lowest idx on tie
            if (acc[i][j] > bestv) { bestv = acc[i][j]; bj = j; }
        const int gcol = bn + n0 + ((bj < 4) ? bj : 12 + bj);
        const unsigned long long pk =
            ((unsigned long long)f2key(bestv) << 32) |
            (unsigned long long)(0xFFFFFFFFu - (unsigned int)gcol);  // smaller idx wins ties
        const int lrow = m0 + ((i < 4) ? i : 28 + i);
        atomicMax(&sbest[lrow], pk);
    }
    __syncthreads();

    if (tid < 128) {
        const int grow = bm + tid;
        if (grow < NTOK) atomicMax(&g_best[grow], sbest[tid]);
    }
}

// ---------------- K3: gather W[idx], write outputs, loss + usage marking ----------------
// block = token, thread = channel
__global__ void k_output(const float* __restrict__ cls,
                         const float* __restrict__ patch,
                         const float* __restrict__ W,
                         float* __restrict__ out) {
    const int t = blockIdx.x;
    const int c = threadIdx.x;
    const int b = t / 257, j = t % 257;

    const int code = (int)(0xFFFFFFFFu - (unsigned int)(g_best[t] & 0xFFFFFFFFull));
    const float w = W[code * WIDTH + c];                   // coalesced row read
    const float x = (j == 0) ? cls[b * WIDTH + c]
                             : patch[b * 65536 + c * 256 + (j - 1)];
    const float d = w - x;
    const float s = block_reduce_sum_256(d * d);
    if (c == 0) {
        atomicAdd(&g_loss, (double)s);
        g_used[code] = 1;
    }
    if (j == 0) out[b * WIDTH + c] = w;                         // fhat_class [B,1,C]
    else        out[8192 + b * 65536 + c * 256 + (j - 1)] = w;  // fhat_patch [B,C,H,W]
}

// ---------------- K4: scalars ----------------
__global__ void k_finalize(float* __restrict__ out) {
    int cnt = 0;
    for (int i = threadIdx.x; i < VOCAB; i += 256) cnt += g_used[i];
    const float s = block_reduce_sum_256((float)cnt);   // exact for <= 16384
    if (threadIdx.x == 0) {
        // vq_loss = (1 + BETA) * mean((W[idx]-x)^2), BETA = 0.25
        out[2105344] = (float)(1.25 * g_loss / (double)(NTOK * WIDTH));
        out[2105345] = 100.0f * s / (float)VOCAB;       // vocab usage %
    }
}

// ---------------- launch ----------------
extern "C" void kernel_launch(void* const* d_in, const int* in_sizes, int n_in,
                              void* d_out, int out_size) {
    // identify inputs by element count (sizes are pairwise distinct)
    const float* cls   = nullptr;   // 32*1*256      = 8192
    const float* patch = nullptr;   // 32*256*16*16  = 2097152
    const float* W     = nullptr;   // 16384*256     = 4194304
    for (int i = 0; i < n_in; i++) {
        if      (in_sizes[i] == NBATCH * WIDTH)          cls   = (const float*)d_in[i];
        else if (in_sizes[i] == NBATCH * WIDTH * 256)    patch = (const float*)d_in[i];
        else if (in_sizes[i] == VOCAB * WIDTH)           W     = (const float*)d_in[i];
    }
    float* out = (float*)d_out;

    k_init<<<VOCAB / 256, 256>>>();
    k_normalize<<<MPAD + VOCAB, 256>>>(cls, patch, W);
    dim3 grid(VOCAB / 128, MPAD / 128);   // (128, 65)
    k_gemm_argmax<<<grid, 256>>>();
    k_output<<<NTOK, 256>>>(cls, patch, W, out);
    k_finalize<<<1, 256>>>(out);
}

// round 10
// speedup vs baseline: 2.4870x; 2.4833x over previous
#include <cuda_runtime.h>
#include <cuda_bf16.h>

#define VOCAB   16384
#define WIDTH   256
#define NTOK    8224      // 32 * 257
#define MPAD    8320      // 65 * 128
#define NBATCH  32

#define KTOT    512       // stored per row: [hi(256) | lo(256)]
#define TM      128
#define TN      128
#define BK      64        // bf16 per k-slab => 128B rows
#define NSLAB   12        // 4x hi*hi + 4x hi*lo + 4x lo*hi
#define STAGE   32768     // A 16KB + B 16KB
#define B_OFF   16384
#define DYN_SMEM (2 * STAGE)

// ---------------- scratch (device globals; no runtime alloc) ----------------
__device__ __align__(16) __nv_bfloat16 g_Abf[MPAD * KTOT];    // 8.5 MB
__device__ __align__(16) __nv_bfloat16 g_Bbf[VOCAB * KTOT];   // 16.8 MB
__device__ unsigned long long  g_best[NTOK];
__device__ int                 g_used[VOCAB];
__device__ double              g_loss;

// ---------------- helpers ----------------
__device__ __forceinline__ float block_reduce_sum_256(float v) {
    __shared__ float red[8];
    const int lane = threadIdx.x & 31;
    const int w    = threadIdx.x >> 5;
    #pragma unroll
    for (int o = 16; o > 0; o >>= 1) v += __shfl_xor_sync(0xffffffffu, v, o);
    if (lane == 0) red[w] = v;
    __syncthreads();
    float s = 0.f;
    #pragma unroll
    for (int i = 0; i < 8; i++) s += red[i];
    return s;
}
__device__ __forceinline__ unsigned int f2key(float v) {
    unsigned int u = __float_as_uint(v);
    return (u & 0x80000000u) ? ~u : (u | 0x80000000u);
}
__device__ __forceinline__ unsigned smem_u32(const void* p) {
    unsigned a;
    asm("{ .reg .u64 t; cvta.to.shared.u64 t, %1; cvt.u32.u64 %0, t; }" : "=r"(a) : "l"(p));
    return a;
}
__device__ __forceinline__ void cp16(unsigned dst, const void* src) {
    asm volatile("cp.async.cg.shared.global [%0], [%1], 16;" :: "r"(dst), "l"(src));
}
#define CP_COMMIT() asm volatile("cp.async.commit_group;" ::: "memory")
#define CP_WAIT1()  asm volatile("cp.async.wait_group 1;"  ::: "memory")
#define CP_WAIT0()  asm volatile("cp.async.wait_group 0;"  ::: "memory")

__device__ __forceinline__ void ldsm4(unsigned& r0, unsigned& r1, unsigned& r2, unsigned& r3,
                                      unsigned addr) {
    asm volatile("ldmatrix.sync.aligned.m8n8.x4.shared.b16 {%0,%1,%2,%3}, [%4];"
                 : "=r"(r0), "=r"(r1), "=r"(r2), "=r"(r3) : "r"(addr));
}
__device__ __forceinline__ void mma_bf16(float* d, const unsigned* a, const unsigned* b) {
    asm volatile(
        "mma.sync.aligned.m16n8k16.row.col.f32.bf16.bf16.f32 "
        "{%0,%1,%2,%3}, {%4,%5,%6,%7}, {%8,%9}, {%0,%1,%2,%3};"
        : "+f"(d[0]), "+f"(d[1]), "+f"(d[2]), "+f"(d[3])
        : "r"(a[0]), "r"(a[1]), "r"(a[2]), "r"(a[3]), "r"(b[0]), "r"(b[1]));
}

// slab t -> (A k-offset, B k-offset) in bf16 elements within a row
__device__ __forceinline__ void slab_off(int t, int& kA, int& kB) {
    kA = (t < 8) ? ((t & 3) << 6) : (((t - 8) << 6) + 256);            // hi,hi,lo
    kB = (t < 4) ? (t << 6) : ((t < 8) ? (((t - 4) << 6) + 256)        // hi,lo,hi
                                       : ((t - 8) << 6));
}

// ---------------- K0: reset per-call state ----------------
__global__ void k_init() {
    const int i = blockIdx.x * blockDim.x + threadIdx.x;
    if (i < NTOK)  g_best[i] = 0ull;
    if (i < VOCAB) g_used[i] = 0;
    if (i == 0)    g_loss    = 0.0;
}

// ---------------- K1: gather + normalize + bf16 hi/lo split ----------------
__global__ void k_normalize(const float* __restrict__ cls,
                            const float* __restrict__ patch,
                            const float* __restrict__ W) {
    const int r = blockIdx.x;
    const int c = threadIdx.x;
    float v = 0.f;
    __nv_bfloat16* dst; long long row;
    if (r < MPAD) {
        if (r < NTOK) {
            const int b = r / 257, j = r % 257;
            v = (j == 0) ? cls[b * WIDTH + c]
                         : patch[b * 65536 + c * 256 + (j - 1)];
        }
        dst = g_Abf; row = r;
    } else {
        row = r - MPAD;
        v = W[row * WIDTH + c];
        dst = g_Bbf;
    }
    const float s   = block_reduce_sum_256(v * v);
    const float inv = 1.f / fmaxf(sqrtf(s), 1e-12f);
    const float xn  = v * inv;
    const __nv_bfloat16 hi = __float2bfloat16(xn);
    const float lo = xn - __bfloat162float(hi);
    dst[row * KTOT + c]       = hi;
    dst[row * KTOT + 256 + c] = __float2bfloat16(lo);
}

// ---------------- stage loader: one (A-chunk, B-chunk) slab ----------------
__device__ __forceinline__ void load_slab(unsigned sb, int bm, int bn,
                                          int kA0, int kB0, int tid) {
    const int ck = tid & 7;            // 16B chunk (8 bf16) within 128B row
    const int r0 = tid >> 3;           // 0..31
    const unsigned cswz = (unsigned)(ck << 4);
    #pragma unroll
    for (int i = 0; i < 4; i++) {
        const int lr = r0 + 32 * i;
        const unsigned off = (unsigned)lr * 128u + (cswz ^ (((unsigned)lr & 7u) << 4));
        cp16(sb + off,         g_Abf + (long long)(bm + lr) * KTOT + kA0 + ck * 8);
        cp16(sb + B_OFF + off, g_Bbf + (long long)(bn + lr) * KTOT + kB0 + ck * 8);
    }
    CP_COMMIT();
}

// ---------------- K2: bf16 mma.sync GEMM (3-term hi/lo split) + argmax ----------------
__global__ __launch_bounds__(256, 2)
void k_gemm_mma() {
    extern __shared__ char dsm[];
    __shared__ unsigned long long sbest[TM];

    const unsigned base = smem_u32(dsm);
    const int tid  = threadIdx.x;
    const int lane = tid & 31;
    const int warp = tid >> 5;
    const int wm   = (warp >> 2) * 64;       // warp m-base (2 warps in m)
    const int wn   = (warp & 3) * 32;        // warp n-base (4 warps in n)
    const int bn   = blockIdx.x * TN;
    const int bm   = blockIdx.y * TM;

    float d[4][4][4];
    #pragma unroll
    for (int i = 0; i < 4; i++)
        #pragma unroll
        for (int j = 0; j < 4; j++)
            #pragma unroll
            for (int k = 0; k < 4; k++) d[i][j][k] = 0.f;

    // ldmatrix lane addressing
    const int lsel = lane & 7;
    const int agrp_r = ((lane >> 3) & 1) * 8;   // A: matrices 1,3 -> +8 rows
    const int agrp_k = ((lane >> 4) & 1) * 16;  // A: matrices 2,3 -> +16B k
    const int bgrp_r = ((lane >> 4) & 1) * 8;   // B: matrices 2,3 -> +8 rows
    const int bgrp_k = ((lane >> 3) & 1) * 16;  // B: matrices 1,3 -> +16B k

    // prologue: slabs 0 and 1
    {
        int kA, kB;
        slab_off(0, kA, kB); load_slab(base,         bm, bn, kA, kB, tid);
        slab_off(1, kA, kB); load_slab(base + STAGE, bm, bn, kA, kB, tid);
    }

    #pragma unroll 1
    for (int t = 0; t < NSLAB; t++) {
        const unsigned sA = base + (t & 1) * STAGE;
        const unsigned sB = sA + B_OFF;
        if (t < NSLAB - 1) CP_WAIT1(); else CP_WAIT0();
        __syncthreads();

        #pragma unroll
        for (int g = 0; g < 4; g++) {           // k16 groups within 64-k slab
            const int kb = g * 32;
            unsigned a[4][4], b[4][2];
            #pragma unroll
            for (int mt = 0; mt < 4; mt++) {
                const int row = wm + mt * 16 + lsel + agrp_r;
                const int kk  = kb + agrp_k;
                ldsm4(a[mt][0], a[mt][1], a[mt][2], a[mt][3],
                      sA + (unsigned)row * 128u + ((unsigned)kk ^ (((unsigned)row & 7u) << 4)));
            }
            #pragma unroll
            for (int np = 0; np < 2; np++) {
                const int row = wn + np * 16 + lsel + bgrp_r;
                const int kk  = kb + bgrp_k;
                unsigned r0, r1, r2, r3;
                ldsm4(r0, r1, r2, r3,
                      sB + (unsigned)row * 128u + ((unsigned)kk ^ (((unsigned)row & 7u) << 4)));
                b[np * 2 + 0][0] = r0; b[np * 2 + 0][1] = r1;
                b[np * 2 + 1][0] = r2; b[np * 2 + 1][1] = r3;
            }
            #pragma unroll
            for (int mt = 0; mt < 4; mt++)
                #pragma unroll
                for (int nt = 0; nt < 4; nt++)
                    mma_bf16(d[mt][nt], a[mt], b[nt]);
        }
        __syncthreads();
        if (t + 2 < NSLAB) {
            int kA, kB;
            slab_off(t + 2, kA, kB);
            load_slab(sA, bm, bn, kA, kB, tid);
        }
    }

    // ---- fused argmax epilogue ----
    if (tid < TM) sbest[tid] = 0ull;
    __syncthreads();

    #pragma unroll
    for (int mt = 0; mt < 4; mt++) {
        #pragma unroll
        for (int rh = 0; rh < 2; rh++) {        // d0/d1 = row, d2/d3 = row+8
            const int lrow = wm + mt * 16 + rh * 8 + (lane >> 2);
            float bestv = -2.0f; int bestc = 0;
            #pragma unroll
            for (int nt = 0; nt < 4; nt++) {
                const int c0 = wn + nt * 8 + (lane & 3) * 2;  // ascending col order
                const float v0 = d[mt][nt][rh * 2 + 0];
                const float v1 = d[mt][nt][rh * 2 + 1];
                if (v0 > bestv) { bestv = v0; bestc = c0; }
                if (v1 > bestv) { bestv = v1; bestc = c0 + 1; }
            }
            const unsigned long long pk =
                ((unsigned long long)f2key(bestv) << 32) |
                (unsigned long long)(0xFFFFFFFFu - (unsigned)(bn + bestc));
            atomicMax(&sbest[lrow], pk);
        }
    }
    __syncthreads();

    if (tid < TM) {
        const int grow = bm + tid;
        if (grow < NTOK) atomicMax(&g_best[grow], sbest[tid]);
    }
}

// ---------------- K3: gather W[idx], outputs, loss + usage ----------------
__global__ void k_output(const float* __restrict__ cls,
                         const float* __restrict__ patch,
                         const float* __restrict__ W,
                         float* __restrict__ out) {
    const int t = blockIdx.x;
    const int c = threadIdx.x;
    const int b = t / 257, j = t % 257;

    const int code = (int)(0xFFFFFFFFu - (unsigned int)(g_best[t] & 0xFFFFFFFFull));
    const float w = W[code * WIDTH + c];
    const float x = (j == 0) ? cls[b * WIDTH + c]
                             : patch[b * 65536 + c * 256 + (j - 1)];
    const float dd = w - x;
    const float s = block_reduce_sum_256(dd * dd);
    if (c == 0) {
        atomicAdd(&g_loss, (double)s);
        g_used[code] = 1;
    }
    if (j == 0) out[b * WIDTH + c] = w;                         // fhat_class [B,1,C]
    else        out[8192 + b * 65536 + c * 256 + (j - 1)] = w;  // fhat_patch [B,C,H,W]
}

// ---------------- K4: scalars ----------------
__global__ void k_finalize(float* __restrict__ out) {
    int cnt = 0;
    for (int i = threadIdx.x; i < VOCAB; i += 256) cnt += g_used[i];
    const float s = block_reduce_sum_256((float)cnt);
    if (threadIdx.x == 0) {
        out[2105344] = (float)(1.25 * g_loss / (double)(NTOK * WIDTH));
        out[2105345] = 100.0f * s / (float)VOCAB;
    }
}

// ---------------- launch ----------------
extern "C" void kernel_launch(void* const* d_in, const int* in_sizes, int n_in,
                              void* d_out, int out_size) {
    const float* cls   = nullptr;
    const float* patch = nullptr;
    const float* W     = nullptr;
    for (int i = 0; i < n_in; i++) {
        if      (in_sizes[i] == NBATCH * WIDTH)          cls   = (const float*)d_in[i];
        else if (in_sizes[i] == NBATCH * WIDTH * 256)    patch = (const float*)d_in[i];
        else if (in_sizes[i] == VOCAB * WIDTH)           W     = (const float*)d_in[i];
    }
    float* out = (float*)d_out;

    cudaFuncSetAttribute(k_gemm_mma, cudaFuncAttributeMaxDynamicSharedMemorySize, DYN_SMEM);

    k_init<<<VOCAB / 256, 256>>>();
    k_normalize<<<MPAD + VOCAB, 256>>>(cls, patch, W);
    dim3 grid(VOCAB / TN, MPAD / TM);   // (128, 65)
    k_gemm_mma<<<grid, 256, DYN_SMEM>>>();
    k_output<<<NTOK, 256>>>(cls, patch, W, out);
    k_finalize<<<1, 256>>>(out);
}